// round 1
// baseline (speedup 1.0000x reference)
#include <cuda_runtime.h>
#include <cuda_bf16.h>

// ---------------------------------------------------------------------------
// S4D model forward:  encoder GEMM -> 4x( S4 scan + gelu -> GEMM -> GLU+res+LN )
//                     -> decoder GEMM
// B=32, L=1024, D_IN=128, H=256, N2=32 modes, 4 layers, D_OUT=10
// FFT long-conv replaced by the exactly-equivalent diagonal recurrence.
// GEMMs use packed fp32x2 FMA (fma.rn.f32x2).
// ---------------------------------------------------------------------------

#define BSZ    32
#define LSEQ   1024
#define DIN    128
#define HDIM   256
#define NL     4
#define NMODE  32
#define DOUT   10
#define MROWS  (BSZ * LSEQ)          // 32768
#define HN     (HDIM * NMODE)        // 8192

// Scratch (device globals; no allocation allowed)
__device__ __align__(128) float g_h[MROWS * HDIM];       // residual stream
__device__ __align__(128) float g_y[MROWS * HDIM];       // gelu(S4 out)
__device__ __align__(128) float g_z[MROWS * 2 * HDIM];   // pre-GLU linear out
__device__ __align__(128) float g_coef[NL * 6 * HN];     // dAre,dAim,dBre,dBim,2Cre,-2Cim

typedef unsigned long long ull;

__device__ __forceinline__ ull pack2(float x) {
    ull r; asm("mov.b64 %0, {%1, %1};" : "=l"(r) : "f"(x)); return r;
}
__device__ __forceinline__ ull fma2(ull a, ull b, ull c) {
    ull d; asm("fma.rn.f32x2 %0, %1, %2, %3;" : "=l"(d) : "l"(a), "l"(b), "l"(c)); return d;
}
union U2 { ull u; float2 f; };
union U4 { float4 f4; ull u[2]; };

__device__ __forceinline__ float gelu_f(float x) {
    float x3 = x * x * x;
    float t  = tanhf(0.7978845608028654f * fmaf(0.044715f, x3, x));
    return 0.5f * x * (1.0f + t);
}

// ---------------------------------------------------------------------------
// Discretization prep: per (layer, h, n) compute ZOH params.
// dA = exp(dt*A),  dB = B*(dA-1)/A,  fold factor 2 into C.
// ---------------------------------------------------------------------------
__global__ void prep_coef(const float* __restrict__ log_dt,
                          const float* __restrict__ A_re_log,
                          const float* __restrict__ A_im,
                          const float* __restrict__ B_re,
                          const float* __restrict__ B_im,
                          const float* __restrict__ C_re,
                          const float* __restrict__ C_im)
{
    int t = blockIdx.x * 256 + threadIdx.x;
    if (t >= NL * HN) return;
    int l  = t / HN;
    int hn = t - l * HN;
    int hh = hn / NMODE;

    float Are = -expf(A_re_log[t]);
    float Aim = A_im[t];
    float dt  = expf(log_dt[l * HDIM + hh]);
    float dre = dt * Are, dim = dt * Aim;
    float e   = expf(dre);
    float dAre = e * cosf(dim);
    float dAim = e * sinf(dim);
    // (dA - 1) / A  =  (dA-1) * conj(A) / |A|^2
    float nre = dAre - 1.0f, nim = dAim;
    float inv = 1.0f / (Are * Are + Aim * Aim);
    float qre = (nre * Are + nim * Aim) * inv;
    float qim = (nim * Are - nre * Aim) * inv;
    float bre = B_re[t], bim = B_im[t];
    float dBre = bre * qre - bim * qim;
    float dBim = bre * qim + bim * qre;

    float* cf = g_coef + (size_t)l * 6 * HN;
    cf[0 * HN + hn] = dAre;
    cf[1 * HN + hn] = dAim;
    cf[2 * HN + hn] = dBre;
    cf[3 * HN + hn] = dBim;
    cf[4 * HN + hn] =  2.0f * C_re[t];
    cf[5 * HN + hn] = -2.0f * C_im[t];
}

// ---------------------------------------------------------------------------
// SGEMM with bias, fp32x2 packed accumulation.
// C[M,N] = A[M,K] @ B[K,N] + bias[N].  BM=BN=128, BK=8, 256 thr, 8x8 microtile.
// M=32768 (div 128), N in {256,512}, K in {128,256} as template.
// ---------------------------------------------------------------------------
template <int NK>
__global__ __launch_bounds__(256) void sgemm_bias(
    const float* __restrict__ A, const float* __restrict__ Bw,
    const float* __restrict__ bias, float* __restrict__ C, int N)
{
    constexpr int BM = 128, BN = 128, BK = 8, TM = 8;
    __shared__ float As[BK][BM];
    __shared__ float Bs[BK][BN];

    const int tid  = threadIdx.x;
    const float* Ap = A + (size_t)blockIdx.y * BM * NK;
    const float* Bp = Bw + blockIdx.x * BN;

    const int rA = tid >> 1;             // 0..127
    const int cA = (tid & 1) * 4;        // 0 or 4
    const int rB = tid >> 5;             // 0..7
    const int cB = (tid & 31) * 4;       // 0..124
    const int tRow = (tid >> 4) * TM;
    const int tCol = (tid & 15) * 8;

    ull acc[TM][4];
#pragma unroll
    for (int i = 0; i < TM; i++)
#pragma unroll
        for (int j = 0; j < 4; j++) acc[i][j] = 0ull;

    for (int k0 = 0; k0 < NK; k0 += BK) {
        float4 av = *reinterpret_cast<const float4*>(Ap + rA * NK + cA);
        As[cA + 0][rA] = av.x; As[cA + 1][rA] = av.y;
        As[cA + 2][rA] = av.z; As[cA + 3][rA] = av.w;
        *reinterpret_cast<float4*>(&Bs[rB][cB]) =
            *reinterpret_cast<const float4*>(Bp + (size_t)rB * N + cB);
        __syncthreads();
        Ap += BK;
        Bp += (size_t)BK * N;
#pragma unroll
        for (int k = 0; k < BK; k++) {
            float4 a0 = *reinterpret_cast<const float4*>(&As[k][tRow]);
            float4 a1 = *reinterpret_cast<const float4*>(&As[k][tRow + 4]);
            U4 b0, b1;
            b0.f4 = *reinterpret_cast<const float4*>(&Bs[k][tCol]);
            b1.f4 = *reinterpret_cast<const float4*>(&Bs[k][tCol + 4]);
            float am[8] = {a0.x, a0.y, a0.z, a0.w, a1.x, a1.y, a1.z, a1.w};
            ull   bp[4] = {b0.u[0], b0.u[1], b1.u[0], b1.u[1]};
#pragma unroll
            for (int i = 0; i < TM; i++) {
                ull ad = pack2(am[i]);
#pragma unroll
                for (int j = 0; j < 4; j++) acc[i][j] = fma2(ad, bp[j], acc[i][j]);
            }
        }
        __syncthreads();
    }

    float bb[8];
#pragma unroll
    for (int j = 0; j < 8; j++) bb[j] = bias[blockIdx.x * BN + tCol + j];

    float* Cp = C + ((size_t)(blockIdx.y * BM + tRow)) * N + blockIdx.x * BN + tCol;
#pragma unroll
    for (int i = 0; i < TM; i++) {
        U2 p0, p1, p2, p3;
        p0.u = acc[i][0]; p1.u = acc[i][1]; p2.u = acc[i][2]; p3.u = acc[i][3];
        float4 o0 = make_float4(p0.f.x + bb[0], p0.f.y + bb[1], p1.f.x + bb[2], p1.f.y + bb[3]);
        float4 o1 = make_float4(p2.f.x + bb[4], p2.f.y + bb[5], p3.f.x + bb[6], p3.f.y + bb[7]);
        *reinterpret_cast<float4*>(Cp)     = o0;
        *reinterpret_cast<float4*>(Cp + 4) = o1;
        Cp += N;
    }
}

// ---------------------------------------------------------------------------
// S4D diagonal recurrence + D*u skip + gelu.
// Block = 256 thr (8 warps) owns batch b, channels h0..h0+31.
// Each 8-lane group = one channel; each lane holds 4 complex modes.
// u staged through smem in 64-step chunks (coalesced 128B lines).
// ---------------------------------------------------------------------------
__global__ __launch_bounds__(256) void s4_scan(
    const float* __restrict__ u, float* __restrict__ y,
    const float* __restrict__ cf, const float* __restrict__ Dv)
{
    const int b    = blockIdx.y;
    const int h0   = blockIdx.x * 32;
    const int tid  = threadIdx.x;
    const int w    = tid >> 5;
    const int lane = tid & 31;
    const int g    = lane >> 3;          // seq (channel) within warp, 0..3
    const int mg   = (lane & 7) * 4;     // first of this lane's 4 modes
    const int hcol = (w << 2) + g;       // channel within block, 0..31
    const int hh   = h0 + hcol;          // global channel

    float dAre[4], dAim[4], dBre[4], dBim[4], c2re[4], c2in[4];
#pragma unroll
    for (int j = 0; j < 4; j++) {
        int ci  = hh * NMODE + mg + j;
        dAre[j] = cf[0 * HN + ci];
        dAim[j] = cf[1 * HN + ci];
        dBre[j] = cf[2 * HN + ci];
        dBim[j] = cf[3 * HN + ci];
        c2re[j] = cf[4 * HN + ci];
        c2in[j] = cf[5 * HN + ci];
    }

    __shared__ float su[64 * 32];
    __shared__ float sy[64 * 32];
    __shared__ float sD[32];
    if (tid < 32) sD[tid] = Dv[h0 + tid];

    float sre[4] = {0.f, 0.f, 0.f, 0.f};
    float sim[4] = {0.f, 0.f, 0.f, 0.f};

    const float* ub = u + ((size_t)b * LSEQ) * HDIM + h0;
    float*       yb = y + ((size_t)b * LSEQ) * HDIM + h0;

    for (int l0 = 0; l0 < LSEQ; l0 += 64) {
        __syncthreads();
#pragma unroll
        for (int k = 0; k < 8; k++) {
            int e = tid + k * 256;
            su[e] = ub[(size_t)(l0 + (e >> 5)) * HDIM + (e & 31)];
        }
        __syncthreads();
#pragma unroll 4
        for (int i = 0; i < 64; i++) {
            float uu = su[i * 32 + hcol];
            float c = 0.0f;
#pragma unroll
            for (int j = 0; j < 4; j++) {
                float nre = fmaf(dAre[j], sre[j], -(dAim[j] * sim[j]));
                nre = fmaf(dBre[j], uu, nre);
                float nim = fmaf(dAre[j], sim[j], dAim[j] * sre[j]);
                nim = fmaf(dBim[j], uu, nim);
                sre[j] = nre; sim[j] = nim;
                c = fmaf(c2re[j], nre, c);
                c = fmaf(c2in[j], nim, c);
            }
            c += __shfl_xor_sync(0xffffffffu, c, 1);
            c += __shfl_xor_sync(0xffffffffu, c, 2);
            c += __shfl_xor_sync(0xffffffffu, c, 4);
            if ((lane & 7) == 0) sy[i * 32 + hcol] = c;
        }
        __syncthreads();
#pragma unroll
        for (int k = 0; k < 8; k++) {
            int e = tid + k * 256;
            float t = sy[e] + sD[e & 31] * su[e];
            yb[(size_t)(l0 + (e >> 5)) * HDIM + (e & 31)] = gelu_f(t);
        }
    }
}

// ---------------------------------------------------------------------------
// GLU + residual + LayerNorm (in-place on h).  Warp per row of 256.
// ---------------------------------------------------------------------------
__global__ __launch_bounds__(256) void glu_res_ln(
    const float* __restrict__ z, float* __restrict__ h,
    const float* __restrict__ lnw, const float* __restrict__ lnb)
{
    const int row  = blockIdx.x * 8 + (threadIdx.x >> 5);
    const int lane = threadIdx.x & 31;
    const float* zr = z + (size_t)row * (2 * HDIM);
    float*       hr = h + (size_t)row * HDIM;

    float tv[8];
    float s = 0.f, s2 = 0.f;
#pragma unroll
    for (int k = 0; k < 8; k++) {
        int c = lane + k * 32;
        float a  = zr[c];
        float gg = zr[HDIM + c];
        float t  = a / (1.0f + expf(-gg)) + hr[c];
        tv[k] = t;
        s  += t;
        s2  = fmaf(t, t, s2);
    }
#pragma unroll
    for (int o = 16; o; o >>= 1) {
        s  += __shfl_xor_sync(0xffffffffu, s,  o);
        s2 += __shfl_xor_sync(0xffffffffu, s2, o);
    }
    float mean = s * (1.0f / 256.0f);
    float var  = fmaf(-mean, mean, s2 * (1.0f / 256.0f));
    float rs   = rsqrtf(var + 1e-5f);
#pragma unroll
    for (int k = 0; k < 8; k++) {
        int c = lane + k * 32;
        hr[c] = fmaf((tv[k] - mean) * rs, lnw[c], lnb[c]);
    }
}

// ---------------------------------------------------------------------------
// Decoder: out[M,10] = h[M,256] @ dec_w[256,10] + dec_b.
// ---------------------------------------------------------------------------
__global__ __launch_bounds__(256) void decoder(
    const float* __restrict__ h, const float* __restrict__ w,
    const float* __restrict__ bvec, float* __restrict__ out)
{
    __shared__ float sw[HDIM * DOUT];
    for (int i = threadIdx.x; i < HDIM * DOUT; i += 256) sw[i] = w[i];
    __syncthreads();
    int o = blockIdx.x * 256 + threadIdx.x;
    int r = o / DOUT, n = o - r * DOUT;
    const float* hr = h + (size_t)r * HDIM;
    float s = bvec[n];
#pragma unroll 8
    for (int k = 0; k < HDIM; k++) s = fmaf(hr[k], sw[k * DOUT + n], s);
    out[o] = s;
}

// ---------------------------------------------------------------------------
extern "C" void kernel_launch(void* const* d_in, const int* in_sizes, int n_in,
                              void* d_out, int out_size)
{
    const float* x        = (const float*)d_in[0];
    const float* enc_w    = (const float*)d_in[1];
    const float* enc_b    = (const float*)d_in[2];
    const float* log_dt   = (const float*)d_in[3];
    const float* A_re_log = (const float*)d_in[4];
    const float* A_im     = (const float*)d_in[5];
    const float* B_re     = (const float*)d_in[6];
    const float* B_im     = (const float*)d_in[7];
    const float* C_re     = (const float*)d_in[8];
    const float* C_im     = (const float*)d_in[9];
    const float* Dp       = (const float*)d_in[10];
    const float* ln_w     = (const float*)d_in[11];
    const float* ln_b     = (const float*)d_in[12];
    const float* out_w    = (const float*)d_in[13];
    const float* out_b    = (const float*)d_in[14];
    const float* dec_w    = (const float*)d_in[15];
    const float* dec_b    = (const float*)d_in[16];
    float* outp = (float*)d_out;

    float *ph, *py, *pz, *pcf;
    cudaGetSymbolAddress((void**)&ph,  g_h);
    cudaGetSymbolAddress((void**)&py,  g_y);
    cudaGetSymbolAddress((void**)&pz,  g_z);
    cudaGetSymbolAddress((void**)&pcf, g_coef);

    // discretization constants for all layers
    prep_coef<<<(NL * HN + 255) / 256, 256>>>(log_dt, A_re_log, A_im,
                                              B_re, B_im, C_re, C_im);
    // encoder: h = x @ enc_w + enc_b
    sgemm_bias<DIN><<<dim3(HDIM / 128, MROWS / 128), 256>>>(x, enc_w, enc_b, ph, HDIM);

    for (int l = 0; l < NL; l++) {
        s4_scan<<<dim3(HDIM / 32, BSZ), 256>>>(ph, py,
                                               pcf + (size_t)l * 6 * HN,
                                               Dp + l * HDIM);
        sgemm_bias<HDIM><<<dim3(2 * HDIM / 128, MROWS / 128), 256>>>(
            py, out_w + (size_t)l * HDIM * 2 * HDIM, out_b + l * 2 * HDIM,
            pz, 2 * HDIM);
        glu_res_ln<<<MROWS / 8, 256>>>(pz, ph, ln_w + l * HDIM, ln_b + l * HDIM);
    }

    decoder<<<(MROWS * DOUT) / 256, 256>>>(ph, dec_w, dec_b, outp);
}

// round 5
// speedup vs baseline: 1.2671x; 1.2671x over previous
#include <cuda_runtime.h>
#include <cuda_bf16.h>
#include <cstdint>

// ---------------------------------------------------------------------------
// S4D model forward:  encoder GEMM -> 4x( S4 scan+gelu -> GEMM -> GLU+res+LN )
//                     -> decoder
// GEMMs: legacy mma.sync m16n8k16 bf16 with 3-pass hi/lo split (fp32-accurate).
// Scan: diagonal recurrence with packed fp32x2 FMA.
// ---------------------------------------------------------------------------

#define BSZ    32
#define LSEQ   1024
#define DIN    128
#define HDIM   256
#define NL     4
#define NMODE  32
#define DOUT   10
#define MROWS  (BSZ * LSEQ)          // 32768
#define HN     (HDIM * NMODE)        // 8192

// Scratch (device globals; no allocation allowed)
__device__ __align__(128) float g_h[MROWS * HDIM];
__device__ __align__(128) float g_y[MROWS * HDIM];
__device__ __align__(128) float g_z[MROWS * 2 * HDIM];
__device__ __align__(128) float g_coef[NL * 6 * HN];
__device__ __align__(16) __nv_bfloat16 g_wthi_enc[HDIM * DIN];   // [N=256][K=128]
__device__ __align__(16) __nv_bfloat16 g_wtlo_enc[HDIM * DIN];
__device__ __align__(16) __nv_bfloat16 g_wthi[NL * 2 * HDIM * HDIM]; // [512][256] x4
__device__ __align__(16) __nv_bfloat16 g_wtlo[NL * 2 * HDIM * HDIM];

typedef unsigned long long ull;

__device__ __forceinline__ ull pack2(float x) {
    ull r; asm("mov.b64 %0, {%1, %1};" : "=l"(r) : "f"(x)); return r;
}
__device__ __forceinline__ ull packf(float a, float b) {
    ull r; asm("mov.b64 %0, {%1, %2};" : "=l"(r) : "f"(a), "f"(b)); return r;
}
__device__ __forceinline__ ull fma2(ull a, ull b, ull c) {
    ull d; asm("fma.rn.f32x2 %0, %1, %2, %3;" : "=l"(d) : "l"(a), "l"(b), "l"(c)); return d;
}
union U2 { ull u; float2 f; };

__device__ __forceinline__ uint32_t smem_u32(const void* p) {
    uint32_t a;
    asm("{ .reg .u64 t; cvta.to.shared.u64 t, %1; cvt.u32.u64 %0, t; }"
        : "=r"(a) : "l"(p));
    return a;
}
__device__ __forceinline__ void ldsm4(uint32_t* r, uint32_t addr) {
    asm volatile("ldmatrix.sync.aligned.m8n8.x4.shared.b16 {%0,%1,%2,%3}, [%4];"
                 : "=r"(r[0]), "=r"(r[1]), "=r"(r[2]), "=r"(r[3]) : "r"(addr));
}
__device__ __forceinline__ void mma16816(float* c, const uint32_t* a, const uint32_t* b) {
    asm volatile("mma.sync.aligned.m16n8k16.row.col.f32.bf16.bf16.f32 "
                 "{%0,%1,%2,%3}, {%4,%5,%6,%7}, {%8,%9}, {%0,%1,%2,%3};"
                 : "+f"(c[0]), "+f"(c[1]), "+f"(c[2]), "+f"(c[3])
                 : "r"(a[0]), "r"(a[1]), "r"(a[2]), "r"(a[3]), "r"(b[0]), "r"(b[1]));
}
__device__ __forceinline__ uint32_t pkbf(float a, float b) {
    uint32_t ha = __bfloat16_as_ushort(__float2bfloat16_rn(a));
    uint32_t hb = __bfloat16_as_ushort(__float2bfloat16_rn(b));
    return ha | (hb << 16);
}

__device__ __forceinline__ float gelu_f(float x) {
    float x3 = x * x * x;
    float t  = tanhf(0.7978845608028654f * fmaf(0.044715f, x3, x));
    return 0.5f * x * (1.0f + t);
}

// ---------------------------------------------------------------------------
// Discretization prep
// ---------------------------------------------------------------------------
__global__ void prep_coef(const float* __restrict__ log_dt,
                          const float* __restrict__ A_re_log,
                          const float* __restrict__ A_im,
                          const float* __restrict__ B_re,
                          const float* __restrict__ B_im,
                          const float* __restrict__ C_re,
                          const float* __restrict__ C_im)
{
    int t = blockIdx.x * 256 + threadIdx.x;
    if (t >= NL * HN) return;
    int l  = t / HN;
    int hn = t - l * HN;
    int hh = hn / NMODE;

    float Are = -expf(A_re_log[t]);
    float Aim = A_im[t];
    float dt  = expf(log_dt[l * HDIM + hh]);
    float dre = dt * Are, dim = dt * Aim;
    float e   = expf(dre);
    float dAre = e * cosf(dim);
    float dAim = e * sinf(dim);
    float nre = dAre - 1.0f, nim = dAim;
    float inv = 1.0f / (Are * Are + Aim * Aim);
    float qre = (nre * Are + nim * Aim) * inv;
    float qim = (nim * Are - nre * Aim) * inv;
    float bre = B_re[t], bim = B_im[t];
    float dBre = bre * qre - bim * qim;
    float dBim = bre * qim + bim * qre;

    float* cf = g_coef + (size_t)l * 6 * HN;
    cf[0 * HN + hn] = dAre;
    cf[1 * HN + hn] = dAim;
    cf[2 * HN + hn] = dBre;
    cf[3 * HN + hn] = dBim;
    cf[4 * HN + hn] =  2.0f * C_re[t];
    cf[5 * HN + hn] = -2.0f * C_im[t];
}

// ---------------------------------------------------------------------------
// Weight transpose + bf16 hi/lo split:  W [K][N] fp32 -> Whi/Wlo [N][K] bf16
// ---------------------------------------------------------------------------
__global__ void split_w(const float* __restrict__ W,
                        __nv_bfloat16* __restrict__ Whi,
                        __nv_bfloat16* __restrict__ Wlo, int K, int N)
{
    __shared__ float t[32][33];
    int n0 = blockIdx.x * 32, k0 = blockIdx.y * 32;
    const float* Wp = W + (size_t)blockIdx.z * K * N;
    __nv_bfloat16* Hp = Whi + (size_t)blockIdx.z * K * N;
    __nv_bfloat16* Lp = Wlo + (size_t)blockIdx.z * K * N;
#pragma unroll
    for (int yy = 0; yy < 32; yy += 8)
        t[threadIdx.y + yy][threadIdx.x] =
            Wp[(size_t)(k0 + threadIdx.y + yy) * N + n0 + threadIdx.x];
    __syncthreads();
#pragma unroll
    for (int yy = 0; yy < 32; yy += 8) {
        float v = t[threadIdx.x][threadIdx.y + yy];
        __nv_bfloat16 h = __float2bfloat16_rn(v);
        float r = v - __bfloat162float(h);
        size_t o = (size_t)(n0 + threadIdx.y + yy) * K + k0 + threadIdx.x;
        Hp[o] = h;
        Lp[o] = __float2bfloat16_rn(r);
    }
}

// ---------------------------------------------------------------------------
// bf16 split-3 tensor-core GEMM:  C[M,N] = A[M,K] @ W[K,N] + bias
//   A fp32 row-major (split to hi/lo in-kernel), W pre-split [N][K] bf16.
//   Tiles: BM=128, BN=128, BK=32, 256 threads (8 warps = 4M x 2N),
//   warp tile 32x64 (2 m-frags x 8 n-frags), ldmatrix + mma.sync m16n8k16.
//   SMEM stage: [Ahi 8K][Alo 8K][Bhi 8K][Blo 8K], double buffered (64KB).
//   Swizzle: 16B chunk c at row r stored at c ^ ((r>>1)&3)  (conflict-free).
// ---------------------------------------------------------------------------
template <int K>
__global__ __launch_bounds__(256) void mma_gemm(
    const float* __restrict__ A,
    const __nv_bfloat16* __restrict__ Bhi,
    const __nv_bfloat16* __restrict__ Blo,
    const float* __restrict__ bias,
    float* __restrict__ C, int N)
{
    constexpr int KCH = K / 32;
    extern __shared__ char sm[];
    const uint32_t sbase = smem_u32(sm);

    const int tid  = threadIdx.x;
    const int warp = tid >> 5, lane = tid & 31;
    const int wm = warp >> 1, wn = warp & 1;
    const size_t m0 = (size_t)blockIdx.y * 128;
    const int    n0 = blockIdx.x * 128;

    // prefetch registers: 2 units per thread, each = 8 elems (16B bf16 / 32B fp32)
    float4 afr[2][2];
    uint4  bhfr[2], blfr[2];
    int urow[2], usw[2];
#pragma unroll
    for (int i = 0; i < 2; i++) {
        int u = tid + i * 256;
        int row = u >> 2, c = u & 3;
        urow[i] = row;
        usw[i]  = row * 64 + ((c ^ ((row >> 1) & 3)) << 4);
    }

    auto ldg = [&](int cs) {
#pragma unroll
        for (int i = 0; i < 2; i++) {
            int u = tid + i * 256;
            int row = u >> 2, c = u & 3;
            const float4* pa = (const float4*)(A + (m0 + row) * K + cs * 32 + c * 8);
            afr[i][0] = pa[0];
            afr[i][1] = pa[1];
            bhfr[i] = *(const uint4*)(Bhi + (size_t)(n0 + row) * K + cs * 32 + c * 8);
            blfr[i] = *(const uint4*)(Blo + (size_t)(n0 + row) * K + cs * 32 + c * 8);
        }
    };
    auto sts = [&](int buf) {
        char* st = sm + buf * 32768;
#pragma unroll
        for (int i = 0; i < 2; i++) {
            float f[8] = {afr[i][0].x, afr[i][0].y, afr[i][0].z, afr[i][0].w,
                          afr[i][1].x, afr[i][1].y, afr[i][1].z, afr[i][1].w};
            uint32_t hw[4], lw[4];
#pragma unroll
            for (int j = 0; j < 4; j++) {
                float a = f[2 * j], b = f[2 * j + 1];
                __nv_bfloat16 ha = __float2bfloat16_rn(a);
                __nv_bfloat16 hb = __float2bfloat16_rn(b);
                hw[j] = (uint32_t)__bfloat16_as_ushort(ha) |
                        ((uint32_t)__bfloat16_as_ushort(hb) << 16);
                lw[j] = pkbf(a - __bfloat162float(ha), b - __bfloat162float(hb));
            }
            *(uint4*)(st + usw[i])         = make_uint4(hw[0], hw[1], hw[2], hw[3]);
            *(uint4*)(st + 8192 + usw[i])  = make_uint4(lw[0], lw[1], lw[2], lw[3]);
            *(uint4*)(st + 16384 + usw[i]) = bhfr[i];
            *(uint4*)(st + 24576 + usw[i]) = blfr[i];
        }
    };

    float acc[2][8][4];
#pragma unroll
    for (int a = 0; a < 2; a++)
#pragma unroll
        for (int b = 0; b < 8; b++)
#pragma unroll
            for (int c = 0; c < 4; c++) acc[a][b][c] = 0.f;

    auto compute = [&](int buf) {
        uint32_t ab = sbase + buf * 32768;
#pragma unroll
        for (int ks = 0; ks < 2; ks++) {
            uint32_t ah[2][4], al[2][4], bh[8][2], bl[8][2];
#pragma unroll
            for (int mt = 0; mt < 2; mt++) {
                int r  = wm * 32 + mt * 16 + (lane & 15);
                int ch = ks * 2 + (lane >> 4);
                uint32_t addr = ab + r * 64 + ((ch ^ ((r >> 1) & 3)) << 4);
                ldsm4(ah[mt], addr);
                ldsm4(al[mt], addr + 8192);
            }
#pragma unroll
            for (int j = 0; j < 4; j++) {
                int r  = wn * 64 + j * 16 + (lane & 15);
                int ch = ks * 2 + (lane >> 4);
                uint32_t addr = ab + 16384 + r * 64 + ((ch ^ ((r >> 1) & 3)) << 4);
                uint32_t q[4];
                ldsm4(q, addr);
                bh[2 * j][0] = q[0]; bh[2 * j + 1][0] = q[1];
                bh[2 * j][1] = q[2]; bh[2 * j + 1][1] = q[3];
                ldsm4(q, addr + 8192);
                bl[2 * j][0] = q[0]; bl[2 * j + 1][0] = q[1];
                bl[2 * j][1] = q[2]; bl[2 * j + 1][1] = q[3];
            }
#pragma unroll
            for (int mt = 0; mt < 2; mt++)
#pragma unroll
                for (int nt = 0; nt < 8; nt++) {
                    mma16816(acc[mt][nt], ah[mt], bh[nt]);
                    mma16816(acc[mt][nt], al[mt], bh[nt]);
                    mma16816(acc[mt][nt], ah[mt], bl[nt]);
                }
        }
    };

    ldg(0);
    sts(0);
    __syncthreads();
    for (int c = 0; c < KCH; c++) {
        if (c + 1 < KCH) ldg(c + 1);
        compute(c & 1);
        if (c + 1 < KCH) sts((c + 1) & 1);
        __syncthreads();
    }

    // epilogue: + bias, fp32 store
#pragma unroll
    for (int mt = 0; mt < 2; mt++) {
#pragma unroll
        for (int nt = 0; nt < 8; nt++) {
            int r = (int)m0 + wm * 32 + mt * 16 + (lane >> 2);
            int n = n0 + wn * 64 + nt * 8 + (lane & 3) * 2;
            float b0 = bias[n], b1 = bias[n + 1];
            *(float2*)(C + (size_t)r * N + n) =
                make_float2(acc[mt][nt][0] + b0, acc[mt][nt][1] + b1);
            *(float2*)(C + (size_t)(r + 8) * N + n) =
                make_float2(acc[mt][nt][2] + b0, acc[mt][nt][3] + b1);
        }
    }
}

// ---------------------------------------------------------------------------
// S4D diagonal recurrence + D*u skip + gelu, modes packed into fp32x2.
// Block = 256 thr owns batch b, channels h0..h0+31; 8 lanes/channel,
// 4 modes/lane = 2 packed complex pairs.
// ---------------------------------------------------------------------------
__global__ __launch_bounds__(256) void s4_scan(
    const float* __restrict__ u, float* __restrict__ y,
    const float* __restrict__ cf, const float* __restrict__ Dv)
{
    const int b    = blockIdx.y;
    const int h0   = blockIdx.x * 32;
    const int tid  = threadIdx.x;
    const int w    = tid >> 5;
    const int lane = tid & 31;
    const int g    = lane >> 3;
    const int mg   = (lane & 7) * 4;
    const int hcol = (w << 2) + g;
    const int hh   = h0 + hcol;

    ull dAre2[2], dAim2[2], ndAim2[2], dBre2[2], dBim2[2], c2re2[2], c2in2[2];
#pragma unroll
    for (int p = 0; p < 2; p++) {
        int c0 = hh * NMODE + mg + 2 * p;
        int c1 = c0 + 1;
        dAre2[p]  = packf(cf[0 * HN + c0], cf[0 * HN + c1]);
        dAim2[p]  = packf(cf[1 * HN + c0], cf[1 * HN + c1]);
        ndAim2[p] = packf(-cf[1 * HN + c0], -cf[1 * HN + c1]);
        dBre2[p]  = packf(cf[2 * HN + c0], cf[2 * HN + c1]);
        dBim2[p]  = packf(cf[3 * HN + c0], cf[3 * HN + c1]);
        c2re2[p]  = packf(cf[4 * HN + c0], cf[4 * HN + c1]);
        c2in2[p]  = packf(cf[5 * HN + c0], cf[5 * HN + c1]);
    }

    __shared__ float su[64 * 32];
    __shared__ float sy[64 * 32];
    __shared__ float sD[32];
    if (tid < 32) sD[tid] = Dv[h0 + tid];

    ull sre2[2] = {0ull, 0ull};
    ull sim2[2] = {0ull, 0ull};

    const float* ub = u + ((size_t)b * LSEQ) * HDIM + h0;
    float*       yb = y + ((size_t)b * LSEQ) * HDIM + h0;

    for (int l0 = 0; l0 < LSEQ; l0 += 64) {
        __syncthreads();
#pragma unroll
        for (int k = 0; k < 8; k++) {
            int e = tid + k * 256;
            su[e] = ub[(size_t)(l0 + (e >> 5)) * HDIM + (e & 31)];
        }
        __syncthreads();
#pragma unroll 4
        for (int i = 0; i < 64; i++) {
            float uu = su[i * 32 + hcol];
            ull uu2  = pack2(uu);
            ull cacc = 0ull;
#pragma unroll
            for (int p = 0; p < 2; p++) {
                ull mre = fma2(dBre2[p], uu2, 0ull);
                ull mim = fma2(dBim2[p], uu2, 0ull);
                ull nre = fma2(ndAim2[p], sim2[p], mre);
                nre     = fma2(dAre2[p],  sre2[p], nre);
                ull nim = fma2(dAim2[p],  sre2[p], mim);
                nim     = fma2(dAre2[p],  sim2[p], nim);
                sre2[p] = nre; sim2[p] = nim;
                cacc = fma2(c2re2[p], nre, cacc);
                cacc = fma2(c2in2[p], nim, cacc);
            }
            U2 cu; cu.u = cacc;
            float c = cu.f.x + cu.f.y;
            c += __shfl_xor_sync(0xffffffffu, c, 1);
            c += __shfl_xor_sync(0xffffffffu, c, 2);
            c += __shfl_xor_sync(0xffffffffu, c, 4);
            if ((lane & 7) == 0) sy[i * 32 + hcol] = c;
        }
        __syncthreads();
#pragma unroll
        for (int k = 0; k < 8; k++) {
            int e = tid + k * 256;
            float t = sy[e] + sD[e & 31] * su[e];
            yb[(size_t)(l0 + (e >> 5)) * HDIM + (e & 31)] = gelu_f(t);
        }
    }
}

// ---------------------------------------------------------------------------
// GLU + residual + LayerNorm (in-place on h).  Warp per row of 256.
// (z already contains bias from the GEMM epilogue.)
// ---------------------------------------------------------------------------
__global__ __launch_bounds__(256) void glu_res_ln(
    const float* __restrict__ z, float* __restrict__ h,
    const float* __restrict__ lnw, const float* __restrict__ lnb)
{
    const int row  = blockIdx.x * 8 + (threadIdx.x >> 5);
    const int lane = threadIdx.x & 31;
    const float* zr = z + (size_t)row * (2 * HDIM);
    float*       hr = h + (size_t)row * HDIM;

    float tv[8];
    float s = 0.f, s2 = 0.f;
#pragma unroll
    for (int k = 0; k < 8; k++) {
        int c = lane + k * 32;
        float a  = zr[c];
        float gg = zr[HDIM + c];
        float t  = a / (1.0f + expf(-gg)) + hr[c];
        tv[k] = t;
        s  += t;
        s2  = fmaf(t, t, s2);
    }
#pragma unroll
    for (int o = 16; o; o >>= 1) {
        s  += __shfl_xor_sync(0xffffffffu, s,  o);
        s2 += __shfl_xor_sync(0xffffffffu, s2, o);
    }
    float mean = s * (1.0f / 256.0f);
    float var  = fmaf(-mean, mean, s2 * (1.0f / 256.0f));
    float rs   = rsqrtf(var + 1e-5f);
#pragma unroll
    for (int k = 0; k < 8; k++) {
        int c = lane + k * 32;
        hr[c] = fmaf((tv[k] - mean) * rs, lnw[c], lnb[c]);
    }
}

// ---------------------------------------------------------------------------
// Decoder: out[M,10] = h[M,256] @ dec_w[256,10] + dec_b
// ---------------------------------------------------------------------------
__global__ __launch_bounds__(256) void decoder(
    const float* __restrict__ h, const float* __restrict__ wv,
    const float* __restrict__ bvec, float* __restrict__ out)
{
    __shared__ float sw[HDIM * DOUT];
    for (int i = threadIdx.x; i < HDIM * DOUT; i += 256) sw[i] = wv[i];
    __syncthreads();
    int o = blockIdx.x * 256 + threadIdx.x;
    int r = o / DOUT, n = o - r * DOUT;
    const float* hr = h + (size_t)r * HDIM;
    float s = bvec[n];
#pragma unroll 8
    for (int k = 0; k < HDIM; k++) s = fmaf(hr[k], sw[k * DOUT + n], s);
    out[o] = s;
}

// ---------------------------------------------------------------------------
extern "C" void kernel_launch(void* const* d_in, const int* in_sizes, int n_in,
                              void* d_out, int out_size)
{
    const float* x        = (const float*)d_in[0];
    const float* enc_w    = (const float*)d_in[1];
    const float* enc_b    = (const float*)d_in[2];
    const float* log_dt   = (const float*)d_in[3];
    const float* A_re_log = (const float*)d_in[4];
    const float* A_im     = (const float*)d_in[5];
    const float* B_re     = (const float*)d_in[6];
    const float* B_im     = (const float*)d_in[7];
    const float* C_re     = (const float*)d_in[8];
    const float* C_im     = (const float*)d_in[9];
    const float* Dp       = (const float*)d_in[10];
    const float* ln_w     = (const float*)d_in[11];
    const float* ln_b     = (const float*)d_in[12];
    const float* out_w    = (const float*)d_in[13];
    const float* out_b    = (const float*)d_in[14];
    const float* dec_w    = (const float*)d_in[15];
    const float* dec_b    = (const float*)d_in[16];
    float* outp = (float*)d_out;

    float *ph, *py, *pz, *pcf;
    __nv_bfloat16 *pwhE, *pwlE, *pwh, *pwl;
    cudaGetSymbolAddress((void**)&ph,  g_h);
    cudaGetSymbolAddress((void**)&py,  g_y);
    cudaGetSymbolAddress((void**)&pz,  g_z);
    cudaGetSymbolAddress((void**)&pcf, g_coef);
    cudaGetSymbolAddress((void**)&pwhE, g_wthi_enc);
    cudaGetSymbolAddress((void**)&pwlE, g_wtlo_enc);
    cudaGetSymbolAddress((void**)&pwh, g_wthi);
    cudaGetSymbolAddress((void**)&pwl, g_wtlo);

    cudaFuncSetAttribute(mma_gemm<128>,
                         cudaFuncAttributeMaxDynamicSharedMemorySize, 65536);
    cudaFuncSetAttribute(mma_gemm<256>,
                         cudaFuncAttributeMaxDynamicSharedMemorySize, 65536);

    prep_coef<<<(NL * HN + 255) / 256, 256>>>(log_dt, A_re_log, A_im,
                                              B_re, B_im, C_re, C_im);
    // enc_w [128][256] -> [256][128] hi/lo
    split_w<<<dim3(HDIM / 32, DIN / 32, 1), dim3(32, 8)>>>(enc_w, pwhE, pwlE,
                                                           DIN, HDIM);
    // out_w[l] [256][512] -> [512][256] hi/lo
    split_w<<<dim3(2 * HDIM / 32, HDIM / 32, NL), dim3(32, 8)>>>(out_w, pwh, pwl,
                                                                 HDIM, 2 * HDIM);

    // encoder: h = x @ enc_w + enc_b   (M=32768, N=256, K=128)
    mma_gemm<128><<<dim3(2, MROWS / 128), 256, 65536>>>(x, pwhE, pwlE, enc_b,
                                                        ph, HDIM);

    for (int l = 0; l < NL; l++) {
        s4_scan<<<dim3(HDIM / 32, BSZ), 256>>>(ph, py,
                                               pcf + (size_t)l * 6 * HN,
                                               Dp + l * HDIM);
        // z = y @ out_w + out_b   (N=512, K=256)
        mma_gemm<256><<<dim3(4, MROWS / 128), 256, 65536>>>(
            py, pwh + (size_t)l * 2 * HDIM * HDIM,
            pwl + (size_t)l * 2 * HDIM * HDIM,
            out_b + l * 2 * HDIM, pz, 2 * HDIM);
        glu_res_ln<<<MROWS / 8, 256>>>(pz, ph, ln_w + l * HDIM, ln_b + l * HDIM);
    }

    decoder<<<(MROWS * DOUT) / 256, 256>>>(ph, dec_w, dec_b, outp);
}

// round 6
// speedup vs baseline: 1.2871x; 1.0158x over previous
#include <cuda_runtime.h>
#include <cuda_bf16.h>
#include <cstdint>

// ---------------------------------------------------------------------------
// S4D model forward:  encoder GEMM -> 4x( S4 scan+gelu -> GEMM -> GLU+res+LN )
//                     -> decoder
// GEMMs: mma.sync m16n8k16 bf16, 3-pass hi/lo split, 2 CTAs/SM.
// Scan:  time-chunked (8 chunks) 3-phase linear-recurrence decomposition,
//        packed fp32x2 FMA, 4 lanes/channel.
// ---------------------------------------------------------------------------

#define BSZ    32
#define LSEQ   1024
#define DIN    128
#define HDIM   256
#define NL     4
#define NMODE  32
#define DOUT   10
#define MROWS  (BSZ * LSEQ)          // 32768
#define HN     (HDIM * NMODE)        // 8192
#define NCH    8                     // time chunks
#define CHL    (LSEQ / NCH)          // 128 steps per chunk

// Scratch (device globals; no allocation allowed)
__device__ __align__(128) float g_h[MROWS * HDIM];
__device__ __align__(128) float g_y[MROWS * HDIM];
__device__ __align__(128) float g_z[MROWS * 2 * HDIM];
__device__ __align__(128) float g_coef[NL * 8 * HN];
__device__ __align__(128) float g_sre[BSZ * NCH * HN];
__device__ __align__(128) float g_sim[BSZ * NCH * HN];
__device__ __align__(16) __nv_bfloat16 g_wthi_enc[HDIM * DIN];
__device__ __align__(16) __nv_bfloat16 g_wtlo_enc[HDIM * DIN];
__device__ __align__(16) __nv_bfloat16 g_wthi[NL * 2 * HDIM * HDIM];
__device__ __align__(16) __nv_bfloat16 g_wtlo[NL * 2 * HDIM * HDIM];

typedef unsigned long long ull;

__device__ __forceinline__ ull pack2(float x) {
    ull r; asm("mov.b64 %0, {%1, %1};" : "=l"(r) : "f"(x)); return r;
}
__device__ __forceinline__ ull packf(float a, float b) {
    ull r; asm("mov.b64 %0, {%1, %2};" : "=l"(r) : "f"(a), "f"(b)); return r;
}
__device__ __forceinline__ ull fma2(ull a, ull b, ull c) {
    ull d; asm("fma.rn.f32x2 %0, %1, %2, %3;" : "=l"(d) : "l"(a), "l"(b), "l"(c)); return d;
}
union U2 { ull u; float2 f; };

__device__ __forceinline__ uint32_t smem_u32(const void* p) {
    uint32_t a;
    asm("{ .reg .u64 t; cvta.to.shared.u64 t, %1; cvt.u32.u64 %0, t; }"
        : "=r"(a) : "l"(p));
    return a;
}
__device__ __forceinline__ void ldsm4(uint32_t* r, uint32_t addr) {
    asm volatile("ldmatrix.sync.aligned.m8n8.x4.shared.b16 {%0,%1,%2,%3}, [%4];"
                 : "=r"(r[0]), "=r"(r[1]), "=r"(r[2]), "=r"(r[3]) : "r"(addr));
}
__device__ __forceinline__ void mma16816(float* c, const uint32_t* a, const uint32_t* b) {
    asm volatile("mma.sync.aligned.m16n8k16.row.col.f32.bf16.bf16.f32 "
                 "{%0,%1,%2,%3}, {%4,%5,%6,%7}, {%8,%9}, {%0,%1,%2,%3};"
                 : "+f"(c[0]), "+f"(c[1]), "+f"(c[2]), "+f"(c[3])
                 : "r"(a[0]), "r"(a[1]), "r"(a[2]), "r"(a[3]), "r"(b[0]), "r"(b[1]));
}
__device__ __forceinline__ uint32_t pkbf(float a, float b) {
    uint32_t ha = __bfloat16_as_ushort(__float2bfloat16_rn(a));
    uint32_t hb = __bfloat16_as_ushort(__float2bfloat16_rn(b));
    return ha | (hb << 16);
}

__device__ __forceinline__ float gelu_f(float x) {
    float x3 = x * x * x;
    float t  = tanhf(0.7978845608028654f * fmaf(0.044715f, x3, x));
    return 0.5f * x * (1.0f + t);
}

// ---------------------------------------------------------------------------
// Discretization prep.  Planes: 0 dAre, 1 dAim, 2 dBre, 3 dBim, 4 2Cre,
// 5 -2Cim, 6/7 = (dA^CHL) re/im for the cross-chunk fix-up.
// ---------------------------------------------------------------------------
__global__ void prep_coef(const float* __restrict__ log_dt,
                          const float* __restrict__ A_re_log,
                          const float* __restrict__ A_im,
                          const float* __restrict__ B_re,
                          const float* __restrict__ B_im,
                          const float* __restrict__ C_re,
                          const float* __restrict__ C_im)
{
    int t = blockIdx.x * 256 + threadIdx.x;
    if (t >= NL * HN) return;
    int l  = t / HN;
    int hn = t - l * HN;
    int hh = hn / NMODE;

    float Are = -expf(A_re_log[t]);
    float Aim = A_im[t];
    float dt  = expf(log_dt[l * HDIM + hh]);
    float dre = dt * Are, dim = dt * Aim;
    float e   = expf(dre);
    float dAre = e * cosf(dim);
    float dAim = e * sinf(dim);
    float nre = dAre - 1.0f, nim = dAim;
    float inv = 1.0f / (Are * Are + Aim * Aim);
    float qre = (nre * Are + nim * Aim) * inv;
    float qim = (nim * Are - nre * Aim) * inv;
    float bre = B_re[t], bim = B_im[t];
    float dBre = bre * qre - bim * qim;
    float dBim = bre * qim + bim * qre;

    float eL = expf((float)CHL * dre);
    float cL = cosf((float)CHL * dim);
    float sL = sinf((float)CHL * dim);

    float* cf = g_coef + (size_t)l * 8 * HN;
    cf[0 * HN + hn] = dAre;
    cf[1 * HN + hn] = dAim;
    cf[2 * HN + hn] = dBre;
    cf[3 * HN + hn] = dBim;
    cf[4 * HN + hn] =  2.0f * C_re[t];
    cf[5 * HN + hn] = -2.0f * C_im[t];
    cf[6 * HN + hn] = eL * cL;
    cf[7 * HN + hn] = eL * sL;
}

// ---------------------------------------------------------------------------
// Weight transpose + bf16 hi/lo split
// ---------------------------------------------------------------------------
__global__ void split_w(const float* __restrict__ W,
                        __nv_bfloat16* __restrict__ Whi,
                        __nv_bfloat16* __restrict__ Wlo, int K, int N)
{
    __shared__ float t[32][33];
    int n0 = blockIdx.x * 32, k0 = blockIdx.y * 32;
    const float* Wp = W + (size_t)blockIdx.z * K * N;
    __nv_bfloat16* Hp = Whi + (size_t)blockIdx.z * K * N;
    __nv_bfloat16* Lp = Wlo + (size_t)blockIdx.z * K * N;
#pragma unroll
    for (int yy = 0; yy < 32; yy += 8)
        t[threadIdx.y + yy][threadIdx.x] =
            Wp[(size_t)(k0 + threadIdx.y + yy) * N + n0 + threadIdx.x];
    __syncthreads();
#pragma unroll
    for (int yy = 0; yy < 32; yy += 8) {
        float v = t[threadIdx.x][threadIdx.y + yy];
        __nv_bfloat16 h = __float2bfloat16_rn(v);
        float r = v - __bfloat162float(h);
        size_t o = (size_t)(n0 + threadIdx.y + yy) * K + k0 + threadIdx.x;
        Hp[o] = h;
        Lp[o] = __float2bfloat16_rn(r);
    }
}

// ---------------------------------------------------------------------------
// bf16 split-3 tensor-core GEMM (2 CTAs/SM)
// ---------------------------------------------------------------------------
template <int K>
__global__ __launch_bounds__(256, 2) void mma_gemm(
    const float* __restrict__ A,
    const __nv_bfloat16* __restrict__ Bhi,
    const __nv_bfloat16* __restrict__ Blo,
    const float* __restrict__ bias,
    float* __restrict__ C, int N)
{
    constexpr int KCH = K / 32;
    extern __shared__ char sm[];
    const uint32_t sbase = smem_u32(sm);

    const int tid  = threadIdx.x;
    const int warp = tid >> 5, lane = tid & 31;
    const int wm = warp >> 1, wn = warp & 1;
    const size_t m0 = (size_t)blockIdx.y * 128;
    const int    n0 = blockIdx.x * 128;

    float4 afr[2][2];
    uint4  bhfr[2], blfr[2];
    int usw[2];
#pragma unroll
    for (int i = 0; i < 2; i++) {
        int u = tid + i * 256;
        int row = u >> 2, c = u & 3;
        usw[i]  = row * 64 + ((c ^ ((row >> 1) & 3)) << 4);
    }

    auto ldg = [&](int cs) {
#pragma unroll
        for (int i = 0; i < 2; i++) {
            int u = tid + i * 256;
            int row = u >> 2, c = u & 3;
            const float4* pa = (const float4*)(A + (m0 + row) * K + cs * 32 + c * 8);
            afr[i][0] = pa[0];
            afr[i][1] = pa[1];
            bhfr[i] = *(const uint4*)(Bhi + (size_t)(n0 + row) * K + cs * 32 + c * 8);
            blfr[i] = *(const uint4*)(Blo + (size_t)(n0 + row) * K + cs * 32 + c * 8);
        }
    };
    auto sts = [&](int buf) {
        char* st = sm + buf * 32768;
#pragma unroll
        for (int i = 0; i < 2; i++) {
            float f[8] = {afr[i][0].x, afr[i][0].y, afr[i][0].z, afr[i][0].w,
                          afr[i][1].x, afr[i][1].y, afr[i][1].z, afr[i][1].w};
            uint32_t hw[4], lw[4];
#pragma unroll
            for (int j = 0; j < 4; j++) {
                float a = f[2 * j], b = f[2 * j + 1];
                __nv_bfloat16 ha = __float2bfloat16_rn(a);
                __nv_bfloat16 hb = __float2bfloat16_rn(b);
                hw[j] = (uint32_t)__bfloat16_as_ushort(ha) |
                        ((uint32_t)__bfloat16_as_ushort(hb) << 16);
                lw[j] = pkbf(a - __bfloat162float(ha), b - __bfloat162float(hb));
            }
            *(uint4*)(st + usw[i])         = make_uint4(hw[0], hw[1], hw[2], hw[3]);
            *(uint4*)(st + 8192 + usw[i])  = make_uint4(lw[0], lw[1], lw[2], lw[3]);
            *(uint4*)(st + 16384 + usw[i]) = bhfr[i];
            *(uint4*)(st + 24576 + usw[i]) = blfr[i];
        }
    };

    float acc[2][8][4];
#pragma unroll
    for (int a = 0; a < 2; a++)
#pragma unroll
        for (int b = 0; b < 8; b++)
#pragma unroll
            for (int c = 0; c < 4; c++) acc[a][b][c] = 0.f;

    auto compute = [&](int buf) {
        uint32_t ab = sbase + buf * 32768;
#pragma unroll
        for (int ks = 0; ks < 2; ks++) {
            uint32_t ah[2][4], al[2][4], bh[8][2], bl[8][2];
#pragma unroll
            for (int mt = 0; mt < 2; mt++) {
                int r  = wm * 32 + mt * 16 + (lane & 15);
                int ch = ks * 2 + (lane >> 4);
                uint32_t addr = ab + r * 64 + ((ch ^ ((r >> 1) & 3)) << 4);
                ldsm4(ah[mt], addr);
                ldsm4(al[mt], addr + 8192);
            }
#pragma unroll
            for (int j = 0; j < 4; j++) {
                int r  = wn * 64 + j * 16 + (lane & 15);
                int ch = ks * 2 + (lane >> 4);
                uint32_t addr = ab + 16384 + r * 64 + ((ch ^ ((r >> 1) & 3)) << 4);
                uint32_t q[4];
                ldsm4(q, addr);
                bh[2 * j][0] = q[0]; bh[2 * j + 1][0] = q[1];
                bh[2 * j][1] = q[2]; bh[2 * j + 1][1] = q[3];
                ldsm4(q, addr + 8192);
                bl[2 * j][0] = q[0]; bl[2 * j + 1][0] = q[1];
                bl[2 * j][1] = q[2]; bl[2 * j + 1][1] = q[3];
            }
#pragma unroll
            for (int mt = 0; mt < 2; mt++)
#pragma unroll
                for (int nt = 0; nt < 8; nt++) {
                    mma16816(acc[mt][nt], ah[mt], bh[nt]);
                    mma16816(acc[mt][nt], al[mt], bh[nt]);
                    mma16816(acc[mt][nt], ah[mt], bl[nt]);
                }
        }
    };

    ldg(0);
    sts(0);
    __syncthreads();
    for (int c = 0; c < KCH; c++) {
        if (c + 1 < KCH) ldg(c + 1);
        compute(c & 1);
        if (c + 1 < KCH) sts((c + 1) & 1);
        __syncthreads();
    }

#pragma unroll
    for (int mt = 0; mt < 2; mt++) {
#pragma unroll
        for (int nt = 0; nt < 8; nt++) {
            int r = (int)m0 + wm * 32 + mt * 16 + (lane >> 2);
            int n = n0 + wn * 64 + nt * 8 + (lane & 3) * 2;
            float b0 = bias[n], b1 = bias[n + 1];
            *(float2*)(C + (size_t)r * N + n) =
                make_float2(acc[mt][nt][0] + b0, acc[mt][nt][1] + b1);
            *(float2*)(C + (size_t)(r + 8) * N + n) =
                make_float2(acc[mt][nt][2] + b0, acc[mt][nt][3] + b1);
        }
    }
}

// ---------------------------------------------------------------------------
// Scan lane mapping (phases A and C):  block = 128 thr owns (batch, 32 chans,
// one time chunk).  4 lanes per channel, 8 modes per lane (4 packed pairs).
// ---------------------------------------------------------------------------
#define SCAN_COEF_LOAD(NP)                                                    \
    ull dAre2[NP], dAim2[NP], ndAim2[NP], dBre2[NP], dBim2[NP];               \
    _Pragma("unroll")                                                         \
    for (int p = 0; p < NP; p++) {                                            \
        int c0 = hh * NMODE + mg + 2 * p;                                     \
        dAre2[p]  = packf(cf[0 * HN + c0], cf[0 * HN + c0 + 1]);              \
        dAim2[p]  = packf(cf[1 * HN + c0], cf[1 * HN + c0 + 1]);              \
        ndAim2[p] = packf(-cf[1 * HN + c0], -cf[1 * HN + c0 + 1]);            \
        dBre2[p]  = packf(cf[2 * HN + c0], cf[2 * HN + c0 + 1]);              \
        dBim2[p]  = packf(cf[3 * HN + c0], cf[3 * HN + c0 + 1]);              \
    }

// Phase A: local end-state per chunk (zero init), chunks 0..NCH-2
__global__ __launch_bounds__(128) void s4_state(
    const float* __restrict__ u, const float* __restrict__ cf)
{
    const int b     = blockIdx.y;
    const int chunk = blockIdx.z;
    const int h0    = blockIdx.x * 32;
    const int tid   = threadIdx.x;
    const int w     = tid >> 5;
    const int lane  = tid & 31;
    const int hcol  = (w << 3) + (lane >> 2);   // 0..31
    const int mg    = (lane & 3) * 8;           // first of 8 modes
    const int hh    = h0 + hcol;

    SCAN_COEF_LOAD(4)

    __shared__ float su[64 * 32];
    ull sre2[4] = {0ull, 0ull, 0ull, 0ull};
    ull sim2[4] = {0ull, 0ull, 0ull, 0ull};

    const float* ub = u + ((size_t)b * LSEQ + (size_t)chunk * CHL) * HDIM + h0;

    for (int l0 = 0; l0 < CHL; l0 += 64) {
        __syncthreads();
#pragma unroll
        for (int k = 0; k < 16; k++) {
            int e = tid + k * 128;
            su[e] = ub[(size_t)(l0 + (e >> 5)) * HDIM + (e & 31)];
        }
        __syncthreads();
#pragma unroll 4
        for (int i = 0; i < 64; i++) {
            ull uu2 = pack2(su[i * 32 + hcol]);
#pragma unroll
            for (int p = 0; p < 4; p++) {
                ull mre = fma2(dBre2[p], uu2, 0ull);
                ull mim = fma2(dBim2[p], uu2, 0ull);
                ull nre = fma2(ndAim2[p], sim2[p], mre);
                nre     = fma2(dAre2[p],  sre2[p], nre);
                ull nim = fma2(dAim2[p],  sre2[p], mim);
                nim     = fma2(dAre2[p],  sim2[p], nim);
                sre2[p] = nre; sim2[p] = nim;
            }
        }
    }
    size_t sidx = ((size_t)b * NCH + chunk) * HN + hh * NMODE + mg;
#pragma unroll
    for (int p = 0; p < 4; p++) {
        U2 r, q; r.u = sre2[p]; q.u = sim2[p];
        g_sre[sidx + 2 * p]     = r.f.x;
        g_sre[sidx + 2 * p + 1] = r.f.y;
        g_sim[sidx + 2 * p]     = q.f.x;
        g_sim[sidx + 2 * p + 1] = q.f.y;
    }
}

// Phase B: cross-chunk scan: converts local end-states into per-chunk init
// states (in place).  thread per (b, h, n).
__global__ __launch_bounds__(256) void s4_fix(const float* __restrict__ cf)
{
    int t = blockIdx.x * 256 + threadIdx.x;
    if (t >= BSZ * HN) return;
    int b  = t / HN;
    int hn = t - b * HN;
    float pre = cf[6 * HN + hn], pim = cf[7 * HN + hn];
    float Sre = 0.f, Sim = 0.f;
#pragma unroll
    for (int c = 0; c < NCH; c++) {
        size_t idx = ((size_t)b * NCH + c) * HN + hn;
        float ere = 0.f, eim = 0.f;
        if (c < NCH - 1) { ere = g_sre[idx]; eim = g_sim[idx]; }
        g_sre[idx] = Sre;
        g_sim[idx] = Sim;
        float nr = fmaf(pre, Sre, fmaf(-pim, Sim, ere));
        float ni = fmaf(pre, Sim, fmaf(pim, Sre, eim));
        Sre = nr; Sim = ni;
    }
}

// Phase C: full per-chunk scan with init state, producing gelu(y + D*u).
__global__ __launch_bounds__(128) void s4_scan_out(
    const float* __restrict__ u, float* __restrict__ y,
    const float* __restrict__ cf, const float* __restrict__ Dv)
{
    const int b     = blockIdx.y;
    const int chunk = blockIdx.z;
    const int h0    = blockIdx.x * 32;
    const int tid   = threadIdx.x;
    const int w     = tid >> 5;
    const int lane  = tid & 31;
    const int hcol  = (w << 3) + (lane >> 2);
    const int mg    = (lane & 3) * 8;
    const int hh    = h0 + hcol;

    SCAN_COEF_LOAD(4)
    ull c2re2[4], c2in2[4];
#pragma unroll
    for (int p = 0; p < 4; p++) {
        int c0 = hh * NMODE + mg + 2 * p;
        c2re2[p] = packf(cf[4 * HN + c0], cf[4 * HN + c0 + 1]);
        c2in2[p] = packf(cf[5 * HN + c0], cf[5 * HN + c0 + 1]);
    }

    __shared__ float su[64 * 32];
    __shared__ float sy[64 * 32];
    __shared__ float sD[32];
    if (tid < 32) sD[tid] = Dv[h0 + tid];

    ull sre2[4], sim2[4];
    {
        size_t sidx = ((size_t)b * NCH + chunk) * HN + hh * NMODE + mg;
#pragma unroll
        for (int p = 0; p < 4; p++) {
            sre2[p] = packf(g_sre[sidx + 2 * p], g_sre[sidx + 2 * p + 1]);
            sim2[p] = packf(g_sim[sidx + 2 * p], g_sim[sidx + 2 * p + 1]);
        }
    }

    const float* ub = u + ((size_t)b * LSEQ + (size_t)chunk * CHL) * HDIM + h0;
    float*       yb = y + ((size_t)b * LSEQ + (size_t)chunk * CHL) * HDIM + h0;

    for (int l0 = 0; l0 < CHL; l0 += 64) {
        __syncthreads();
#pragma unroll
        for (int k = 0; k < 16; k++) {
            int e = tid + k * 128;
            su[e] = ub[(size_t)(l0 + (e >> 5)) * HDIM + (e & 31)];
        }
        __syncthreads();
#pragma unroll 2
        for (int i = 0; i < 64; i++) {
            ull uu2  = pack2(su[i * 32 + hcol]);
            ull cacc = 0ull;
#pragma unroll
            for (int p = 0; p < 4; p++) {
                ull mre = fma2(dBre2[p], uu2, 0ull);
                ull mim = fma2(dBim2[p], uu2, 0ull);
                ull nre = fma2(ndAim2[p], sim2[p], mre);
                nre     = fma2(dAre2[p],  sre2[p], nre);
                ull nim = fma2(dAim2[p],  sre2[p], mim);
                nim     = fma2(dAre2[p],  sim2[p], nim);
                sre2[p] = nre; sim2[p] = nim;
                cacc = fma2(c2re2[p], nre, cacc);
                cacc = fma2(c2in2[p], nim, cacc);
            }
            U2 cu; cu.u = cacc;
            float c = cu.f.x + cu.f.y;
            c += __shfl_xor_sync(0xffffffffu, c, 1);
            c += __shfl_xor_sync(0xffffffffu, c, 2);
            if ((lane & 3) == 0) sy[i * 32 + hcol] = c;
        }
        __syncthreads();
#pragma unroll
        for (int k = 0; k < 16; k++) {
            int e = tid + k * 128;
            float t = sy[e] + sD[e & 31] * su[e];
            yb[(size_t)(l0 + (e >> 5)) * HDIM + (e & 31)] = gelu_f(t);
        }
    }
}

// ---------------------------------------------------------------------------
// GLU + residual + LayerNorm (in-place on h).  Warp per row of 256.
// ---------------------------------------------------------------------------
__global__ __launch_bounds__(256) void glu_res_ln(
    const float* __restrict__ z, float* __restrict__ h,
    const float* __restrict__ lnw, const float* __restrict__ lnb)
{
    const int row  = blockIdx.x * 8 + (threadIdx.x >> 5);
    const int lane = threadIdx.x & 31;
    const float* zr = z + (size_t)row * (2 * HDIM);
    float*       hr = h + (size_t)row * HDIM;

    float tv[8];
    float s = 0.f, s2 = 0.f;
#pragma unroll
    for (int k = 0; k < 8; k++) {
        int c = lane + k * 32;
        float a  = zr[c];
        float gg = zr[HDIM + c];
        float t  = a / (1.0f + expf(-gg)) + hr[c];
        tv[k] = t;
        s  += t;
        s2  = fmaf(t, t, s2);
    }
#pragma unroll
    for (int o = 16; o; o >>= 1) {
        s  += __shfl_xor_sync(0xffffffffu, s,  o);
        s2 += __shfl_xor_sync(0xffffffffu, s2, o);
    }
    float mean = s * (1.0f / 256.0f);
    float var  = fmaf(-mean, mean, s2 * (1.0f / 256.0f));
    float rs   = rsqrtf(var + 1e-5f);
#pragma unroll
    for (int k = 0; k < 8; k++) {
        int c = lane + k * 32;
        hr[c] = fmaf((tv[k] - mean) * rs, lnw[c], lnb[c]);
    }
}

// ---------------------------------------------------------------------------
// Decoder: out[M,10] = h[M,256] @ dec_w[256,10] + dec_b
// ---------------------------------------------------------------------------
__global__ __launch_bounds__(256) void decoder(
    const float* __restrict__ h, const float* __restrict__ wv,
    const float* __restrict__ bvec, float* __restrict__ out)
{
    __shared__ float sw[HDIM * DOUT];
    for (int i = threadIdx.x; i < HDIM * DOUT; i += 256) sw[i] = wv[i];
    __syncthreads();
    int o = blockIdx.x * 256 + threadIdx.x;
    int r = o / DOUT, n = o - r * DOUT;
    const float* hr = h + (size_t)r * HDIM;
    float s = bvec[n];
#pragma unroll 8
    for (int k = 0; k < HDIM; k++) s = fmaf(hr[k], sw[k * DOUT + n], s);
    out[o] = s;
}

// ---------------------------------------------------------------------------
extern "C" void kernel_launch(void* const* d_in, const int* in_sizes, int n_in,
                              void* d_out, int out_size)
{
    const float* x        = (const float*)d_in[0];
    const float* enc_w    = (const float*)d_in[1];
    const float* enc_b    = (const float*)d_in[2];
    const float* log_dt   = (const float*)d_in[3];
    const float* A_re_log = (const float*)d_in[4];
    const float* A_im     = (const float*)d_in[5];
    const float* B_re     = (const float*)d_in[6];
    const float* B_im     = (const float*)d_in[7];
    const float* C_re     = (const float*)d_in[8];
    const float* C_im     = (const float*)d_in[9];
    const float* Dp       = (const float*)d_in[10];
    const float* ln_w     = (const float*)d_in[11];
    const float* ln_b     = (const float*)d_in[12];
    const float* out_w    = (const float*)d_in[13];
    const float* out_b    = (const float*)d_in[14];
    const float* dec_w    = (const float*)d_in[15];
    const float* dec_b    = (const float*)d_in[16];
    float* outp = (float*)d_out;

    float *ph, *py, *pz, *pcf;
    __nv_bfloat16 *pwhE, *pwlE, *pwh, *pwl;
    cudaGetSymbolAddress((void**)&ph,  g_h);
    cudaGetSymbolAddress((void**)&py,  g_y);
    cudaGetSymbolAddress((void**)&pz,  g_z);
    cudaGetSymbolAddress((void**)&pcf, g_coef);
    cudaGetSymbolAddress((void**)&pwhE, g_wthi_enc);
    cudaGetSymbolAddress((void**)&pwlE, g_wtlo_enc);
    cudaGetSymbolAddress((void**)&pwh, g_wthi);
    cudaGetSymbolAddress((void**)&pwl, g_wtlo);

    cudaFuncSetAttribute(mma_gemm<128>,
                         cudaFuncAttributeMaxDynamicSharedMemorySize, 65536);
    cudaFuncSetAttribute(mma_gemm<256>,
                         cudaFuncAttributeMaxDynamicSharedMemorySize, 65536);

    prep_coef<<<(NL * HN + 255) / 256, 256>>>(log_dt, A_re_log, A_im,
                                              B_re, B_im, C_re, C_im);
    split_w<<<dim3(HDIM / 32, DIN / 32, 1), dim3(32, 8)>>>(enc_w, pwhE, pwlE,
                                                           DIN, HDIM);
    split_w<<<dim3(2 * HDIM / 32, HDIM / 32, NL), dim3(32, 8)>>>(out_w, pwh, pwl,
                                                                 HDIM, 2 * HDIM);

    // encoder: h = x @ enc_w + enc_b   (M=32768, N=256, K=128)
    mma_gemm<128><<<dim3(2, MROWS / 128), 256, 65536>>>(x, pwhE, pwlE, enc_b,
                                                        ph, HDIM);

    for (int l = 0; l < NL; l++) {
        const float* cfl = pcf + (size_t)l * 8 * HN;
        s4_state<<<dim3(HDIM / 32, BSZ, NCH - 1), 128>>>(ph, cfl);
        s4_fix<<<(BSZ * HN + 255) / 256, 256>>>(cfl);
        s4_scan_out<<<dim3(HDIM / 32, BSZ, NCH), 128>>>(ph, py, cfl,
                                                        Dp + l * HDIM);
        mma_gemm<256><<<dim3(4, MROWS / 128), 256, 65536>>>(
            py, pwh + (size_t)l * 2 * HDIM * HDIM,
            pwl + (size_t)l * 2 * HDIM * HDIM,
            out_b + l * 2 * HDIM, pz, 2 * HDIM);
        glu_res_ln<<<MROWS / 8, 256>>>(pz, ph, ln_w + l * HDIM, ln_b + l * HDIM);
    }

    decoder<<<(MROWS * DOUT) / 256, 256>>>(ph, dec_w, dec_b, outp);
}